// round 10
// baseline (speedup 1.0000x reference)
#include <cuda_runtime.h>
#include <cuda_fp16.h>
#include <cstdint>

// Problem constants
#define NL    4
#define HD    1024
#define KK2   2048
#define NJC   2048      // interleaved output cols (even=forcing, odd=tau)
#define MM    8192
#define MAXT  50
#define DTC   0.05f
#define EPS_TAU  1e-6f
#define EPS_CONV 1e-3f

#define STAGE_BYTES 32768          // A 16KB + B 16KB per stage (k-chunk 64, fp16)
#define NSTAGE      3
#define SMEM_BYTES  (NSTAGE * STAGE_BYTES)   // 96KB -> 2 CTAs/SM

// ---------------- device scratch (static: no allocation allowed) ------------
__device__ __half g_W[(size_t)NL * NJC * KK2];   // packed fp16 weights [l][j][k]
__device__ float  g_bias[NL * NJC];              // interleaved biases
__device__ __half g_xh[(size_t)MM * HD];         // fp16 input x
__device__ float  g_stA[(size_t)NL * MM * HD];   // exact states ping
__device__ float  g_stB[(size_t)NL * MM * HD];   // exact states pong
__device__ __half g_shA[(size_t)NL * MM * HD];   // fp16 states ping
__device__ __half g_shB[(size_t)NL * MM * HD];   // fp16 states pong
__device__ int      g_done;
__device__ int      g_tconv;
__device__ unsigned g_maxd;

// ---------------- PTX helpers ----------------
__device__ __forceinline__ unsigned sptr(const void* p) {
    return (unsigned)__cvta_generic_to_shared(p);
}
__device__ __forceinline__ void cpasync16(unsigned dst, const void* src) {
    asm volatile("cp.async.cg.shared.global [%0], [%1], 16;\n" :: "r"(dst), "l"(src));
}
__device__ __forceinline__ void cpcommit() { asm volatile("cp.async.commit_group;\n"); }
template<int N> __device__ __forceinline__ void cpwait() {
    asm volatile("cp.async.wait_group %0;\n" :: "n"(N));
}
__device__ __forceinline__ void ldsm4(unsigned& r0, unsigned& r1, unsigned& r2, unsigned& r3,
                                      unsigned addr) {
    asm volatile("ldmatrix.sync.aligned.m8n8.x4.shared.b16 {%0,%1,%2,%3}, [%4];\n"
                 : "=r"(r0), "=r"(r1), "=r"(r2), "=r"(r3) : "r"(addr));
}
__device__ __forceinline__ void mma_f16(float* c, const unsigned* a, const unsigned* b) {
    asm volatile(
        "mma.sync.aligned.m16n8k16.row.col.f32.f16.f16.f32 "
        "{%0,%1,%2,%3}, {%4,%5,%6,%7}, {%8,%9}, {%0,%1,%2,%3};\n"
        : "+f"(c[0]), "+f"(c[1]), "+f"(c[2]), "+f"(c[3])
        : "r"(a[0]), "r"(a[1]), "r"(a[2]), "r"(a[3]), "r"(b[0]), "r"(b[1]));
}
// Accurate tanh independent of fast-math substitutions
__device__ __forceinline__ float my_tanh(float x) {
    float ax = fabsf(x);
    float e  = __expf(-2.0f * ax);
    float r  = (1.0f - e) / (1.0f + e);
    return copysignf(r, x);
}

// ---------------- pack / init kernels ----------------
__global__ void pack_w_kernel(const float* __restrict__ ws, const float* __restrict__ wi,
                              const float* __restrict__ wt) {
    const size_t total = (size_t)NL * NJC * KK2;
    for (size_t idx = (size_t)blockIdx.x * blockDim.x + threadIdx.x; idx < total;
         idx += (size_t)gridDim.x * blockDim.x) {
        int k = (int)(idx & (KK2 - 1));
        size_t r = idx >> 11;
        int j = (int)(r & (NJC - 1));
        int l = (int)(r >> 11);
        int n = j >> 1;
        float v;
        if (j & 1) v = wt[((size_t)(l * HD + n)) * (2 * HD) + k];
        else       v = (k < HD) ? wi[((size_t)(l * HD + n)) * HD + k]
                                : ws[((size_t)(l * HD + n)) * HD + (k - HD)];
        g_W[idx] = __float2half_rn(v);
    }
}

__global__ void pack_bias_kernel(const float* __restrict__ bs, const float* __restrict__ bi,
                                 const float* __restrict__ bt) {
    int idx = blockIdx.x * blockDim.x + threadIdx.x;
    if (idx < NL * NJC) {
        int j = idx & (NJC - 1);
        int l = idx >> 11;
        int n = j >> 1;
        g_bias[idx] = (j & 1) ? bt[l * HD + n] : (bs[l * HD + n] + bi[l * HD + n]);
    }
}

__global__ void pack_x_kernel(const float* __restrict__ x) {
    const size_t n = (size_t)MM * HD;
    for (size_t i = (size_t)blockIdx.x * blockDim.x + threadIdx.x; i < n;
         i += (size_t)gridDim.x * blockDim.x)
        g_xh[i] = __float2half_rn(x[i]);
}

__global__ void init_states_kernel() {
    const size_t n4 = ((size_t)NL * MM * HD) / 4;
    float4* pa = (float4*)g_stA;
    uint2*  ph = (uint2*)g_shA;
    float4 z = make_float4(0.f, 0.f, 0.f, 0.f);
    uint2  zh = make_uint2(0u, 0u);
    for (size_t i = (size_t)blockIdx.x * blockDim.x + threadIdx.x; i < n4;
         i += (size_t)gridDim.x * blockDim.x) { pa[i] = z; ph[i] = zh; }
    if (blockIdx.x == 0 && threadIdx.x == 0) { g_done = 0; g_tconv = MAXT; g_maxd = 0u; }
}

// ---------------- fused fp16-MMA GEMM + state-update kernel ------------------
// CTA tile: 128 rows x 128 interleaved j-cols (=64 n). 256 threads, 8 warps
// (2M x 4J), 2 CTAs/SM (inter-CTA overlap is load-bearing — R7 lesson).
// 3-stage cp.async pipeline, k-chunk 64, ONE __syncthreads per k-iteration.
__global__ void __launch_bounds__(256, 2) step_layer_kernel(
    const __half* __restrict__ curH, const __half* __restrict__ hinH,
    const float* __restrict__ hinE, float* __restrict__ houtE,
    __half* __restrict__ houtH, const __half* __restrict__ W,
    const float* __restrict__ bias) {
    const int tid   = threadIdx.x;
    const int lane  = tid & 31;
    const int wid   = tid >> 5;
    const int warpM = wid & 1;
    const int warpJ = wid >> 1;       // 0..3
    const int row0  = blockIdx.y * 128;
    const int j0    = blockIdx.x * 128;
    const int nb    = blockIdx.x * 64 + warpJ * 16;
    const int g8    = lane >> 2, tc = lane & 3;

    // Frozen after convergence: propagate exact states only.
    if (*(volatile int*)&g_done) {
        int r   = row0 + (tid >> 1);
        int nb2 = blockIdx.x * 64 + (tid & 1) * 32;
        const float4* s4 = (const float4*)(hinE  + (size_t)r * HD + nb2);
        float4*       d4 = (float4*)(houtE + (size_t)r * HD + nb2);
        #pragma unroll
        for (int i = 0; i < 8; ++i) d4[i] = s4[i];
        return;
    }

    extern __shared__ char smem[];   // 3 stages x [A 16KB | B 16KB]
    const unsigned smemB = sptr(smem);

    float acc[4][4][4];
    #pragma unroll
    for (int a = 0; a < 4; ++a)
        #pragma unroll
        for (int b = 0; b < 4; ++b)
            #pragma unroll
            for (int c = 0; c < 4; ++c) acc[a][b][c] = 0.f;

    const int qr = tid >> 3;   // 0..31
    const int qg = tid & 7;    // 16B group (8 halfs) within a 128B row

    auto load_stage = [&](int kk, int st) {
        const __half* abase = (kk < HD) ? (curH + kk) : (hinH + (kk - HD));
        const __half* bbase = W + kk;
        unsigned aS = smemB + (unsigned)st * STAGE_BYTES;
        unsigned bS = aS + 16384u;
        #pragma unroll
        for (int i = 0; i < 4; ++i) {              // A: 128 rows, B: 128 j-rows
            int r = i * 32 + qr;
            unsigned sw = (unsigned)((r * 8 + (qg ^ (r & 7))) << 4);
            cpasync16(aS + sw, abase + (size_t)(row0 + r) * HD + qg * 8);
            cpasync16(bS + sw, bbase + (size_t)(j0 + r) * KK2 + qg * 8);
        }
    };

    load_stage(0, 0);  cpcommit();
    load_stage(64, 1); cpcommit();

    int stc = 0;   // stage holding data for current kt
    for (int kt = 0; kt < 32; ++kt) {
        if (kt < 31) cpwait<1>(); else cpwait<0>();
        __syncthreads();
        if (kt < 30) {
            int st2 = stc + 2; if (st2 >= 3) st2 -= 3;
            load_stage((kt + 2) * 64, st2);
            cpcommit();
        }
        unsigned aB = smemB + (unsigned)stc * STAGE_BYTES;
        unsigned bB = aB + 16384u;
        if (++stc == 3) stc = 0;

        #pragma unroll
        for (int ks = 0; ks < 4; ++ks) {
            unsigned afr[4][4];
            #pragma unroll
            for (int mt = 0; mt < 4; ++mt) {
                int row = warpM * 64 + mt * 16 + ((lane >> 3) & 1) * 8 + (lane & 7);
                int grp = ks * 2 + ((lane >> 4) & 1);
                unsigned ad = aB + (unsigned)((row * 8 + (grp ^ (row & 7))) << 4);
                ldsm4(afr[mt][0], afr[mt][1], afr[mt][2], afr[mt][3], ad);
            }
            unsigned bfr[4][2];
            #pragma unroll
            for (int p = 0; p < 2; ++p) {
                int jrow = warpJ * 32 + p * 16 + ((lane >> 4) & 1) * 8 + (lane & 7);
                int grp  = ks * 2 + ((lane >> 3) & 1);
                unsigned ad = bB + (unsigned)((jrow * 8 + (grp ^ (jrow & 7))) << 4);
                ldsm4(bfr[p * 2][0], bfr[p * 2][1], bfr[p * 2 + 1][0], bfr[p * 2 + 1][1], ad);
            }
            #pragma unroll
            for (int mt = 0; mt < 4; ++mt)
                #pragma unroll
                for (int nt = 0; nt < 4; ++nt)
                    mma_f16(acc[mt][nt], afr[mt], bfr[nt]);
        }
    }

    // ---- epilogue: liquid-time state update on thread-local (f,tau) pairs ----
    float dmax = 0.f;
    const int rb = row0 + warpM * 64;
    #pragma unroll
    for (int mt = 0; mt < 4; ++mt) {
        #pragma unroll
        for (int nt = 0; nt < 4; ++nt) {
            int n = nb + nt * 4 + tc;
            float2 bb = ((const float2*)bias)[n];   // .x forcing, .y tau
            int r0r = rb + mt * 16 + g8;
            #pragma unroll
            for (int hh = 0; hh < 2; ++hh) {
                int r = r0r + hh * 8;
                float pf = acc[mt][nt][hh * 2 + 0] + bb.x;
                float pt = acc[mt][nt][hh * 2 + 1] + bb.y;
                float h   = hinE[(size_t)r * HD + n];
                float f   = my_tanh(pf);
                float tau = 0.5f * (my_tanh(0.5f * pt) + 1.0f);   // stable sigmoid
                float hn  = h + DTC * (f - h / (tau + EPS_TAU));
                hn = fminf(10.0f, fmaxf(-10.0f, hn));
                houtE[(size_t)r * HD + n] = hn;
                houtH[(size_t)r * HD + n] = __float2half_rn(hn);
                dmax = fmaxf(dmax, fabsf(hn - h));
            }
        }
    }

    #pragma unroll
    for (int o = 16; o > 0; o >>= 1)
        dmax = fmaxf(dmax, __shfl_xor_sync(0xffffffffu, dmax, o));
    float* sred = (float*)smem;   // stage 0 region free after mainloop
    if (lane == 0) sred[wid] = dmax;
    __syncthreads();
    if (tid == 0) {
        float m = sred[0];
        #pragma unroll
        for (int i = 1; i < 8; ++i) m = fmaxf(m, sred[i]);
        atomicMax(&g_maxd, __float_as_uint(m));
    }
}

__global__ void conv_check_kernel(int t) {
    if (!g_done && __uint_as_float(g_maxd) < EPS_CONV) { g_done = 1; g_tconv = t; }
    g_maxd = 0u;
}

__global__ void finalize_kernel(float* __restrict__ out, int out_size) {
    const float* src = g_stA + (size_t)3 * MM * HD;   // layer 3, final parity = A
    const size_t n = (size_t)MM * HD;
    for (size_t i = (size_t)blockIdx.x * blockDim.x + threadIdx.x; i < n;
         i += (size_t)gridDim.x * blockDim.x)
        out[i] = src[i];
    if (blockIdx.x == 0 && threadIdx.x == 0 && (size_t)out_size > n)
        out[n] = (float)g_tconv;
}

// ---------------- host orchestration (graph-capturable) ----------------------
extern "C" void kernel_launch(void* const* d_in, const int* in_sizes, int n_in,
                              void* d_out, int out_size) {
    const float* x  = (const float*)d_in[0];
    const float* ws = (const float*)d_in[1];
    const float* bs = (const float*)d_in[2];
    const float* wi = (const float*)d_in[3];
    const float* bi = (const float*)d_in[4];
    const float* wt = (const float*)d_in[5];
    const float* bt = (const float*)d_in[6];
    (void)in_sizes; (void)n_in;

    cudaFuncSetAttribute(step_layer_kernel,
                         cudaFuncAttributeMaxDynamicSharedMemorySize, SMEM_BYTES);

    float *stA, *stB, *bp;
    __half *shA, *shB, *xh, *Wp;
    cudaGetSymbolAddress((void**)&stA, g_stA);
    cudaGetSymbolAddress((void**)&stB, g_stB);
    cudaGetSymbolAddress((void**)&shA, g_shA);
    cudaGetSymbolAddress((void**)&shB, g_shB);
    cudaGetSymbolAddress((void**)&xh,  g_xh);
    cudaGetSymbolAddress((void**)&Wp,  g_W);
    cudaGetSymbolAddress((void**)&bp,  g_bias);

    pack_w_kernel<<<4096, 256>>>(ws, wi, wt);
    pack_bias_kernel<<<32, 256>>>(bs, bi, bt);
    pack_x_kernel<<<2048, 256>>>(x);
    init_states_kernel<<<512, 256>>>();

    dim3 grid(NJC / 128, MM / 128);   // (16, 64)
    for (int t = 0; t < MAXT; ++t) {
        float*  sinE  = (t & 1) ? stB : stA;
        float*  soutE = (t & 1) ? stA : stB;
        __half* sinH  = (t & 1) ? shB : shA;
        __half* soutH = (t & 1) ? shA : shB;
        const __half* curH = xh;
        for (int l = 0; l < NL; ++l) {
            step_layer_kernel<<<grid, 256, SMEM_BYTES>>>(
                curH,
                sinH  + (size_t)l * MM * HD,
                sinE  + (size_t)l * MM * HD,
                soutE + (size_t)l * MM * HD,
                soutH + (size_t)l * MM * HD,
                Wp + (size_t)l * NJC * KK2,
                bp + l * NJC);
            curH = soutH + (size_t)l * MM * HD;
        }
        conv_check_kernel<<<1, 1>>>(t);
    }
    finalize_kernel<<<2048, 256>>>((float*)d_out, out_size);
}

// round 12
// speedup vs baseline: 1.5478x; 1.5478x over previous
#include <cuda_runtime.h>
#include <cuda_fp16.h>
#include <cstdint>

// Problem constants
#define NL    4
#define HD    1024
#define KK2   2048
#define NJC   2048      // interleaved output cols (even=forcing, odd=tau)
#define MM    8192
#define MAXT  50
#define DTC   0.05f
#define EPS_TAU  1e-6f
#define EPS_CONV 1e-3f

#define STAGE_BYTES 32768          // A 16KB + B 16KB per stage (fp16, k-chunk 64)
#define SMEM_BYTES  (2 * STAGE_BYTES)

// ---------------- device scratch (static: no allocation allowed) ------------
__device__ __half g_W[(size_t)NL * NJC * KK2];   // packed fp16 weights [l][j][k]
__device__ float  g_bias[NL * NJC];              // interleaved biases
__device__ __half g_xh[(size_t)MM * HD];         // fp16 input x
__device__ float  g_stA[(size_t)NL * MM * HD];   // exact states ping
__device__ float  g_stB[(size_t)NL * MM * HD];   // exact states pong
__device__ __half g_shA[(size_t)NL * MM * HD];   // fp16 states ping
__device__ __half g_shB[(size_t)NL * MM * HD];   // fp16 states pong
__device__ int      g_done;
__device__ int      g_tconv;
__device__ unsigned g_maxd;

// ---------------- PTX helpers ----------------
__device__ __forceinline__ unsigned sptr(const void* p) {
    return (unsigned)__cvta_generic_to_shared(p);
}
__device__ __forceinline__ void cpasync16(unsigned dst, const void* src) {
    asm volatile("cp.async.cg.shared.global [%0], [%1], 16;\n" :: "r"(dst), "l"(src));
}
__device__ __forceinline__ void cpcommit() { asm volatile("cp.async.commit_group;\n"); }
template<int N> __device__ __forceinline__ void cpwait() {
    asm volatile("cp.async.wait_group %0;\n" :: "n"(N));
}
__device__ __forceinline__ void ldsm4(unsigned& r0, unsigned& r1, unsigned& r2, unsigned& r3,
                                      unsigned addr) {
    asm volatile("ldmatrix.sync.aligned.m8n8.x4.shared.b16 {%0,%1,%2,%3}, [%4];\n"
                 : "=r"(r0), "=r"(r1), "=r"(r2), "=r"(r3) : "r"(addr));
}
__device__ __forceinline__ void mma_f16(float* c, const unsigned* a, const unsigned* b) {
    asm volatile(
        "mma.sync.aligned.m16n8k16.row.col.f32.f16.f16.f32 "
        "{%0,%1,%2,%3}, {%4,%5,%6,%7}, {%8,%9}, {%0,%1,%2,%3};\n"
        : "+f"(c[0]), "+f"(c[1]), "+f"(c[2]), "+f"(c[3])
        : "r"(a[0]), "r"(a[1]), "r"(a[2]), "r"(a[3]), "r"(b[0]), "r"(b[1]));
}
// Accurate tanh independent of fast-math substitutions
__device__ __forceinline__ float my_tanh(float x) {
    float ax = fabsf(x);
    float e  = __expf(-2.0f * ax);
    float r  = (1.0f - e) / (1.0f + e);
    return copysignf(r, x);
}

// ---------------- pack / init kernels ----------------
__global__ void pack_w_kernel(const float* __restrict__ ws, const float* __restrict__ wi,
                              const float* __restrict__ wt) {
    const size_t total = (size_t)NL * NJC * KK2;
    for (size_t idx = (size_t)blockIdx.x * blockDim.x + threadIdx.x; idx < total;
         idx += (size_t)gridDim.x * blockDim.x) {
        int k = (int)(idx & (KK2 - 1));
        size_t r = idx >> 11;
        int j = (int)(r & (NJC - 1));
        int l = (int)(r >> 11);
        int n = j >> 1;
        float v;
        if (j & 1) v = wt[((size_t)(l * HD + n)) * (2 * HD) + k];
        else       v = (k < HD) ? wi[((size_t)(l * HD + n)) * HD + k]
                                : ws[((size_t)(l * HD + n)) * HD + (k - HD)];
        g_W[idx] = __float2half_rn(v);
    }
}

__global__ void pack_bias_kernel(const float* __restrict__ bs, const float* __restrict__ bi,
                                 const float* __restrict__ bt) {
    int idx = blockIdx.x * blockDim.x + threadIdx.x;
    if (idx < NL * NJC) {
        int j = idx & (NJC - 1);
        int l = idx >> 11;
        int n = j >> 1;
        g_bias[idx] = (j & 1) ? bt[l * HD + n] : (bs[l * HD + n] + bi[l * HD + n]);
    }
}

__global__ void pack_x_kernel(const float* __restrict__ x) {
    const size_t n = (size_t)MM * HD;
    for (size_t i = (size_t)blockIdx.x * blockDim.x + threadIdx.x; i < n;
         i += (size_t)gridDim.x * blockDim.x)
        g_xh[i] = __float2half_rn(x[i]);
}

__global__ void init_states_kernel() {
    const size_t n4 = ((size_t)NL * MM * HD) / 4;
    float4* pa = (float4*)g_stA;
    uint2*  ph = (uint2*)g_shA;
    float4 z = make_float4(0.f, 0.f, 0.f, 0.f);
    uint2  zh = make_uint2(0u, 0u);
    for (size_t i = (size_t)blockIdx.x * blockDim.x + threadIdx.x; i < n4;
         i += (size_t)gridDim.x * blockDim.x) { pa[i] = z; ph[i] = zh; }
    if (blockIdx.x == 0 && threadIdx.x == 0) { g_done = 0; g_tconv = MAXT; g_maxd = 0u; }
}

// ---------------- fused fp16-MMA GEMM + state-update kernel ------------------
// CTA tile: 128 rows x 128 interleaved j-cols (=64 n). 256 threads, 8 warps (2M x 4J),
// 2 CTAs/SM. 2-stage cp.async pipeline, k-chunk 64 (the R6 champion config).
__global__ void __launch_bounds__(256, 2) step_layer_kernel(
    const __half* __restrict__ curH, const __half* __restrict__ hinH,
    const float* __restrict__ hinE, float* __restrict__ houtE,
    __half* __restrict__ houtH, const __half* __restrict__ W,
    const float* __restrict__ bias) {
    const int tid   = threadIdx.x;
    const int lane  = tid & 31;
    const int wid   = tid >> 5;
    const int warpM = wid & 1;
    const int warpJ = wid >> 1;
    const int row0  = blockIdx.y * 128;
    const int j0    = blockIdx.x * 128;
    const int nb    = blockIdx.x * 64 + warpJ * 16;
    const int g8    = lane >> 2, tc = lane & 3;

    // Frozen after convergence: propagate exact states only.
    if (*(volatile int*)&g_done) {
        int r   = row0 + (tid >> 1);
        int nb2 = blockIdx.x * 64 + (tid & 1) * 32;
        const float4* s4 = (const float4*)(hinE  + (size_t)r * HD + nb2);
        float4*       d4 = (float4*)(houtE + (size_t)r * HD + nb2);
        #pragma unroll
        for (int i = 0; i < 8; ++i) d4[i] = s4[i];
        return;
    }

    // L2-prefetch the epilogue's exact-state tile (128 rows x 64 floats = 256 lines,
    // one 128B line per thread) so epilogue LDGs hit L2. Free: overlaps the GEMM.
    {
        const float* pp = hinE + (size_t)(row0 + (tid >> 1)) * HD
                               + blockIdx.x * 64 + (tid & 1) * 32;
        asm volatile("prefetch.global.L2 [%0];" :: "l"(pp));
    }

    extern __shared__ char smem[];   // [A0 16K][B0 16K][A1 16K][B1 16K]
    const unsigned smemB = sptr(smem);

    float acc[4][4][4];
    #pragma unroll
    for (int a = 0; a < 4; ++a)
        #pragma unroll
        for (int b = 0; b < 4; ++b)
            #pragma unroll
            for (int c = 0; c < 4; ++c) acc[a][b][c] = 0.f;

    const int qr = tid >> 3;   // 0..31
    const int qg = tid & 7;    // 16B group (8 halfs) within a 128B row

    auto load_stage = [&](int kk, int st) {
        const __half* abase = (kk < HD) ? (curH + kk) : (hinH + (kk - HD));
        const __half* bbase = W + kk;
        unsigned aS = smemB + (unsigned)st * STAGE_BYTES;
        unsigned bS = aS + 16384u;
        #pragma unroll
        for (int i = 0; i < 4; ++i) {
            int r = i * 32 + qr;
            unsigned sw = (unsigned)((r * 8 + (qg ^ (r & 7))) << 4);
            cpasync16(aS + sw, abase + (size_t)(row0 + r) * HD + qg * 8);
            cpasync16(bS + sw, bbase + (size_t)(j0 + r) * KK2 + qg * 8);
        }
    };

    load_stage(0, 0);
    cpcommit();

    for (int kt = 0; kt < 32; ++kt) {
        if (kt + 1 < 32) { load_stage((kt + 1) * 64, (kt + 1) & 1); cpcommit(); cpwait<1>(); }
        else             { cpwait<0>(); }
        __syncthreads();
        unsigned aB = smemB + (unsigned)(kt & 1) * STAGE_BYTES;
        unsigned bB = aB + 16384u;

        #pragma unroll
        for (int ks = 0; ks < 4; ++ks) {
            unsigned afr[4][4];
            #pragma unroll
            for (int mt = 0; mt < 4; ++mt) {
                int row = warpM * 64 + mt * 16 + ((lane >> 3) & 1) * 8 + (lane & 7);
                int grp = ks * 2 + ((lane >> 4) & 1);
                unsigned ad = aB + (unsigned)((row * 8 + (grp ^ (row & 7))) << 4);
                ldsm4(afr[mt][0], afr[mt][1], afr[mt][2], afr[mt][3], ad);
            }
            unsigned bfr[4][2];
            #pragma unroll
            for (int p = 0; p < 2; ++p) {
                int jrow = warpJ * 32 + p * 16 + ((lane >> 4) & 1) * 8 + (lane & 7);
                int grp  = ks * 2 + ((lane >> 3) & 1);
                unsigned ad = bB + (unsigned)((jrow * 8 + (grp ^ (jrow & 7))) << 4);
                ldsm4(bfr[p * 2][0], bfr[p * 2][1], bfr[p * 2 + 1][0], bfr[p * 2 + 1][1], ad);
            }
            #pragma unroll
            for (int mt = 0; mt < 4; ++mt)
                #pragma unroll
                for (int nt = 0; nt < 4; ++nt)
                    mma_f16(acc[mt][nt], afr[mt], bfr[nt]);
        }
        __syncthreads();
    }

    // ---- epilogue: liquid-time state update on thread-local (f,tau) pairs ----
    float dmax = 0.f;
    const int rb = row0 + warpM * 64;
    #pragma unroll
    for (int mt = 0; mt < 4; ++mt) {
        #pragma unroll
        for (int nt = 0; nt < 4; ++nt) {
            int n = nb + nt * 4 + tc;
            float2 bb = ((const float2*)bias)[n];   // .x forcing, .y tau
            int r0r = rb + mt * 16 + g8;
            #pragma unroll
            for (int hh = 0; hh < 2; ++hh) {
                int r = r0r + hh * 8;
                float pf = acc[mt][nt][hh * 2 + 0] + bb.x;
                float pt = acc[mt][nt][hh * 2 + 1] + bb.y;
                float h   = hinE[(size_t)r * HD + n];
                float f   = my_tanh(pf);
                float tau = 0.5f * (my_tanh(0.5f * pt) + 1.0f);   // stable sigmoid
                float hn  = h + DTC * (f - h / (tau + EPS_TAU));
                hn = fminf(10.0f, fmaxf(-10.0f, hn));
                houtE[(size_t)r * HD + n] = hn;
                houtH[(size_t)r * HD + n] = __float2half_rn(hn);
                dmax = fmaxf(dmax, fabsf(hn - h));
            }
        }
    }

    #pragma unroll
    for (int o = 16; o > 0; o >>= 1)
        dmax = fmaxf(dmax, __shfl_xor_sync(0xffffffffu, dmax, o));
    float* sred = (float*)smem;
    if (lane == 0) sred[wid] = dmax;
    __syncthreads();
    if (tid == 0) {
        float m = sred[0];
        #pragma unroll
        for (int i = 1; i < 8; ++i) m = fmaxf(m, sred[i]);
        atomicMax(&g_maxd, __float_as_uint(m));
    }
}

__global__ void conv_check_kernel(int t) {
    if (!g_done && __uint_as_float(g_maxd) < EPS_CONV) { g_done = 1; g_tconv = t; }
    g_maxd = 0u;
}

__global__ void finalize_kernel(float* __restrict__ out, int out_size) {
    const float* src = g_stA + (size_t)3 * MM * HD;   // layer 3, final parity = A
    const size_t n = (size_t)MM * HD;
    for (size_t i = (size_t)blockIdx.x * blockDim.x + threadIdx.x; i < n;
         i += (size_t)gridDim.x * blockDim.x)
        out[i] = src[i];
    if (blockIdx.x == 0 && threadIdx.x == 0 && (size_t)out_size > n)
        out[n] = (float)g_tconv;
}

// ---------------- host orchestration (graph-capturable) ----------------------
extern "C" void kernel_launch(void* const* d_in, const int* in_sizes, int n_in,
                              void* d_out, int out_size) {
    const float* x  = (const float*)d_in[0];
    const float* ws = (const float*)d_in[1];
    const float* bs = (const float*)d_in[2];
    const float* wi = (const float*)d_in[3];
    const float* bi = (const float*)d_in[4];
    const float* wt = (const float*)d_in[5];
    const float* bt = (const float*)d_in[6];
    (void)in_sizes; (void)n_in;

    cudaFuncSetAttribute(step_layer_kernel,
                         cudaFuncAttributeMaxDynamicSharedMemorySize, SMEM_BYTES);

    float *stA, *stB, *bp;
    __half *shA, *shB, *xh, *Wp;
    cudaGetSymbolAddress((void**)&stA, g_stA);
    cudaGetSymbolAddress((void**)&stB, g_stB);
    cudaGetSymbolAddress((void**)&shA, g_shA);
    cudaGetSymbolAddress((void**)&shB, g_shB);
    cudaGetSymbolAddress((void**)&xh,  g_xh);
    cudaGetSymbolAddress((void**)&Wp,  g_W);
    cudaGetSymbolAddress((void**)&bp,  g_bias);

    pack_w_kernel<<<4096, 256>>>(ws, wi, wt);
    pack_bias_kernel<<<32, 256>>>(bs, bi, bt);
    pack_x_kernel<<<2048, 256>>>(x);
    init_states_kernel<<<512, 256>>>();

    dim3 grid(NJC / 128, MM / 128);   // (16, 64)
    for (int t = 0; t < MAXT; ++t) {
        float*  sinE  = (t & 1) ? stB : stA;
        float*  soutE = (t & 1) ? stA : stB;
        __half* sinH  = (t & 1) ? shB : shA;
        __half* soutH = (t & 1) ? shA : shB;
        const __half* curH = xh;
        for (int l = 0; l < NL; ++l) {
            step_layer_kernel<<<grid, 256, SMEM_BYTES>>>(
                curH,
                sinH  + (size_t)l * MM * HD,
                sinE  + (size_t)l * MM * HD,
                soutE + (size_t)l * MM * HD,
                soutH + (size_t)l * MM * HD,
                Wp + (size_t)l * NJC * KK2,
                bp + l * NJC);
            curH = soutH + (size_t)l * MM * HD;
        }
        conv_check_kernel<<<1, 1>>>(t);
    }
    finalize_kernel<<<2048, 256>>>((float*)d_out, out_size);
}